// round 6
// baseline (speedup 1.0000x reference)
#include <cuda_runtime.h>
#include <math.h>

#define BB 64
#define S1 513
#define SF 512
#define HH 768
#define H4 192           // H/4 float4s per row

// output offsets (float32 flat tuple)
#define OFF_IPRED 0
#define OFF_CPRED 64
#define OFF_ILOSS 32832
#define OFF_CLOSS 32833
#define OFF_TAGS  32834
#define OFF_ISQA  65602

typedef unsigned long long u64;

__device__ __forceinline__ u64 pk2(float lo, float hi) {
    u64 r; asm("mov.b64 %0,{%1,%2};" : "=l"(r) : "f"(lo), "f"(hi)); return r;
}
__device__ __forceinline__ void upk2(u64 v, float& lo, float& hi) {
    asm("mov.b64 {%0,%1}, %2;" : "=f"(lo), "=f"(hi) : "l"(v));
}
__device__ __forceinline__ u64 fadd2(u64 a, u64 b) {
    u64 d; asm("add.rn.f32x2 %0,%1,%2;" : "=l"(d) : "l"(a), "l"(b)); return d;
}
__device__ __forceinline__ void cpa16(void* smem, const void* g) {
    unsigned s = (unsigned)__cvta_generic_to_shared(smem);
    asm volatile("cp.async.cg.shared.global [%0],[%1],16;" :: "r"(s), "l"(g));
}
__device__ __forceinline__ void cpa_commit() {
    asm volatile("cp.async.commit_group;");
}
template <int N> __device__ __forceinline__ void cpa_wait() {
    asm volatile("cp.async.wait_group %0;" :: "n"(N));
}

// scratch (no allocations allowed)
__device__ float4 g_feats[BB * SF];
__device__ float  g_isqa[BB * 2];
__device__ float  g_Z[BB];
__device__ float  g_gold[BB];

// ---------------------------------------------------------------------------
// Kernel A: feats = emb[:,1:] @ crf_W^T + crf_b
// cp.async-staged 4-row tiles, double buffered; 2 tiles per block.
// Accumulation + reduce order bit-identical to prior passing kernel.
// ---------------------------------------------------------------------------
__global__ __launch_bounds__(256) void feats_kernel(
    const float* __restrict__ emb, const float* __restrict__ crf_W,
    const float* __restrict__ crf_b)
{
    __shared__ float4 wc[4 * H4];         // 12 KB
    __shared__ float4 ebuf[2][4 * H4];    // 2 x 12 KB

    const int tid = threadIdx.x;
    for (int i = tid; i < 4 * H4; i += 256) wc[i] = ((const float4*)crf_W)[i];

    const int g0 = blockIdx.x * 2;        // tiles of 4 rows; 8192 tiles total
#pragma unroll
    for (int buf = 0; buf < 2; buf++) {
        int g = g0 + buf;
        int row0 = g * 4;                 // row = b*512 + s
        int b = row0 >> 9;
        int s0 = row0 & 511;
        const float4* src = (const float4*)emb + ((size_t)b * S1 + 1 + s0) * H4;
#pragma unroll
        for (int i = 0; i < 3; i++)
            cpa16(&ebuf[buf][tid + i * 256], src + tid + i * 256);
        cpa_commit();
    }

    const int w = tid >> 5, lane = tid & 31;
    const int r = w & 3, jp = (w >> 2) * 2;
    float4 cb = __ldg((const float4*)crf_b);
    float cb0 = (jp == 0) ? cb.x : cb.z;
    float cb1 = (jp == 0) ? cb.y : cb.w;

#pragma unroll
    for (int buf = 0; buf < 2; buf++) {
        if (buf == 0) cpa_wait<1>(); else cpa_wait<0>();
        __syncthreads();

        float a0 = 0.f, a1 = 0.f;
#pragma unroll
        for (int v = 0; v < 6; v++) {
            int k = lane + v * 32;
            float4 e = ebuf[buf][r * H4 + k];
            float4 w0 = wc[jp * H4 + k];
            float4 w1 = wc[(jp + 1) * H4 + k];
            a0 += e.x * w0.x + e.y * w0.y + e.z * w0.z + e.w * w0.w;
            a1 += e.x * w1.x + e.y * w1.y + e.z * w1.z + e.w * w1.w;
        }
#pragma unroll
        for (int o = 16; o; o >>= 1) {
            a0 += __shfl_xor_sync(0xffffffffu, a0, o);
            a1 += __shfl_xor_sync(0xffffffffu, a1, o);
        }
        if (lane == 0) {
            int row = (g0 + buf) * 4 + r;
            float2 st; st.x = a0 + cb0; st.y = a1 + cb1;
            ((float2*)&g_feats[row])[w >> 2] = st;
        }
    }
}

// ---------------------------------------------------------------------------
// Kernel B: per batch-row CRF. 1 block/row, 8 warps:
//   warp0: segmented log-partition Z (8 segments x 4 basis columns = 32 lanes)
//   warp1 lane0: Viterbi chain (bit-exact) storing deltas to smem
//   warp2: gold score + tags; warp3: isqa CLS GEMV
// then all 256: parallel bp extraction; warp1: parallel integer backtrace.
// ---------------------------------------------------------------------------
__global__ __launch_bounds__(256) void crf_kernel(
    const float* __restrict__ emb, const int* __restrict__ labels,
    const float* __restrict__ transitions, const float* __restrict__ fc2_W,
    float* __restrict__ out)
{
    const int b = blockIdx.x;
    __shared__ float4 sfeat[SF];        // 8 KB, plain t index
    __shared__ float4 sE[SF];           // 8 KB, exp(feat_t), seg-interleaved
    __shared__ float4 sdelta[SF];       // 8 KB
    __shared__ unsigned char sbp[SF];
    __shared__ float str[16];
    __shared__ float sEt[16];
    __shared__ float4 scomp[32];        // segment matrices (columns)
    __shared__ float  scC[8];           // segment exponents

    const int tid = threadIdx.x;
    const float4* gf = &g_feats[b * SF];

    if (tid < 16) {
        float tv = transitions[tid];
        str[tid] = tv;
        sEt[tid] = expf(tv);
    }
    // prologue: stage feats + exp(feats) (interleaved slot = k*8+s)
#pragma unroll
    for (int p = 0; p < 2; p++) {
        int t = tid + p * 256;
        float4 f = gf[t];
        sfeat[t] = f;
        if (t >= 1) {
            int s = (t - 1) >> 6, k = (t - 1) & 63;
            sE[k * 8 + s] = make_float4(__expf(f.x), __expf(f.y), __expf(f.z), __expf(f.w));
        }
    }
    __syncthreads();

    const int warp = tid >> 5, lane = tid & 31;

    if (warp == 0) {
        // ---- segmented Z: lane = (segment s, basis column c) ----
        const int s = lane >> 2, c = lane & 3;
        float Et[16];
#pragma unroll
        for (int i = 0; i < 16; i++) Et[i] = sEt[i];
        float v0 = (c == 0) ? 1.f : 0.f;
        float v1 = (c == 1) ? 1.f : 0.f;
        float v2 = (c == 2) ? 1.f : 0.f;
        float v3 = (c == 3) ? 1.f : 0.f;
        float C2 = 0.f;
        const int nsteps = (s < 7) ? 64 : 63;
        for (int k = 0; k < 64; k++) {
            if (k < nsteps) {
                float4 E = sE[k * 8 + s];
                float q0 = v0 * Et[0] + v1 * Et[4] + v2 * Et[8]  + v3 * Et[12];
                float q1 = v0 * Et[1] + v1 * Et[5] + v2 * Et[9]  + v3 * Et[13];
                float q2 = v0 * Et[2] + v1 * Et[6] + v2 * Et[10] + v3 * Et[14];
                float q3 = v0 * Et[3] + v1 * Et[7] + v2 * Et[11] + v3 * Et[15];
                v0 = q0 * E.x; v1 = q1 * E.y; v2 = q2 * E.z; v3 = q3 * E.w;
            }
            if ((k & 15) == 15) {
                float m = fmaxf(fmaxf(v0, v1), fmaxf(v2, v3));
                m = fmaxf(m, __shfl_xor_sync(0xffffffffu, m, 1));
                m = fmaxf(m, __shfl_xor_sync(0xffffffffu, m, 2));
                int e = (__float_as_int(m) >> 23) - 127;
                C2 += (float)e;
                float sc = __int_as_float((127 - e) << 23);
                v0 *= sc; v1 *= sc; v2 *= sc; v3 *= sc;
            }
        }
        scomp[lane] = make_float4(v0, v1, v2, v3);  // column c of A_s
        if (c == 0) scC[s] = C2;
        __syncwarp(0xffffffffu);
        if (lane == 0) {
            float4 f0 = sfeat[0];
            float p0 = __expf(f0.x + str[8]);
            float p1 = __expf(f0.y + str[9]);
            float p2 = __expf(f0.z + str[10]);
            float p3 = __expf(f0.w + str[11]);
            float Ct = 0.f;
#pragma unroll
            for (int ss = 0; ss < 8; ss++) {
                float4 c0 = scomp[4 * ss], c1 = scomp[4 * ss + 1];
                float4 c2 = scomp[4 * ss + 2], c3 = scomp[4 * ss + 3];
                float q0 = p0 * c0.x + p1 * c1.x + p2 * c2.x + p3 * c3.x;
                float q1 = p0 * c0.y + p1 * c1.y + p2 * c2.y + p3 * c3.y;
                float q2 = p0 * c0.z + p1 * c1.z + p2 * c2.z + p3 * c3.z;
                float q3 = p0 * c0.w + p1 * c1.w + p2 * c2.w + p3 * c3.w;
                Ct += scC[ss];
                float m = fmaxf(fmaxf(q0, q1), fmaxf(q2, q3));
                int e = (__float_as_int(m) >> 23) - 127;
                Ct += (float)e;
                float sc = __int_as_float((127 - e) << 23);
                p0 = q0 * sc; p1 = q1 * sc; p2 = q2 * sc; p3 = q3 * sc;
            }
            float sum = p0 * sEt[3] + p1 * sEt[7] + p2 * sEt[11] + p3 * sEt[15];
            g_Z[b] = (Ct + __log2f(sum)) * 0.69314718055994530942f;
        }
    }

    if (warp == 1 && lane == 0) {
        // ---- Viterbi chain: bit-exact (ADD2 componentwise == scalar FADD) ----
        float tr[16];
#pragma unroll
        for (int i = 0; i < 16; i++) tr[i] = str[i];
        u64 TA0 = pk2(tr[0], tr[4]),   TA1 = pk2(tr[1], tr[5]);
        u64 TA2 = pk2(tr[2], tr[6]),   TA3 = pk2(tr[3], tr[7]);
        u64 TB0 = pk2(tr[8], tr[12]),  TB1 = pk2(tr[9], tr[13]);
        u64 TB2 = pk2(tr[10], tr[14]), TB3 = pk2(tr[11], tr[15]);

        float4 f0 = sfeat[0];
        float d0 = f0.x + tr[8], d1 = f0.y + tr[9], d2 = f0.z + tr[10], d3 = f0.w + tr[11];
        sdelta[0] = make_float4(d0, d1, d2, d3);
        u64 D01 = pk2(d0, d1), D23 = pk2(d2, d3);

#pragma unroll 8
        for (int t = 1; t < SF; t++) {
            float4 f = sfeat[t];
            u64 a0 = fadd2(D01, TA0), a1 = fadd2(D01, TA1);
            u64 a2 = fadd2(D01, TA2), a3 = fadd2(D01, TA3);
            u64 b0 = fadd2(D23, TB0), b1 = fadd2(D23, TB1);
            u64 b2 = fadd2(D23, TB2), b3 = fadd2(D23, TB3);
            float x0,x1,y0,y1,x2,x3,y2,y3,x4,x5,y4,y5,x6,x7,y6,y7;
            upk2(a0,x0,x1); upk2(b0,y0,y1);
            upk2(a1,x2,x3); upk2(b1,y2,y3);
            upk2(a2,x4,x5); upk2(b2,y4,y5);
            upk2(a3,x6,x7); upk2(b3,y6,y7);
            float n0 = fmaxf(fmaxf(x0,x1), fmaxf(y0,y1)) + f.x;
            float n1 = fmaxf(fmaxf(x2,x3), fmaxf(y2,y3)) + f.y;
            float n2 = fmaxf(fmaxf(x4,x5), fmaxf(y4,y5)) + f.z;
            float n3 = fmaxf(fmaxf(x6,x7), fmaxf(y6,y7)) + f.w;
            D01 = pk2(n0, n1); D23 = pk2(n2, n3);
            sdelta[t] = make_float4(n0, n1, n2, n3);
        }
    }

    if (warp == 2) {
        // ---- gold score + tags output ----
        float acc = 0.f;
        const int* lb = labels + b * S1;
        const float* sff = (const float*)sfeat;
        for (int t = lane; t < SF; t += 32) {
            int tg = lb[1 + t];
            acc += sff[t * 4 + tg];
            out[OFF_TAGS + b * SF + t] = (float)tg;
            if (t > 0) { int tp = lb[t]; acc += str[tp * 4 + tg]; }
            else       { acc += str[8 + tg]; }                 // START -> tag0
            if (t == SF - 1) acc += str[tg * 4 + 3];           // tag_last -> STOP
        }
#pragma unroll
        for (int o = 16; o; o >>= 1) acc += __shfl_xor_sync(0xffffffffu, acc, o);
        if (lane == 0) g_gold[b] = acc;
    }

    if (warp == 3) {
        // ---- isqa logits for this row's CLS token (overlapped) ----
        const float4* e4 = (const float4*)emb + (size_t)b * S1 * H4;
        const float4* w4 = (const float4*)fc2_W;
        float a0 = 0.f, a1 = 0.f;
#pragma unroll
        for (int v = 0; v < 6; v++) {
            int k = lane + v * 32;
            float4 e = e4[k];
            float4 w0 = __ldg(w4 + k);
            float4 w1 = __ldg(w4 + H4 + k);
            a0 += e.x * w0.x + e.y * w0.y + e.z * w0.z + e.w * w0.w;
            a1 += e.x * w1.x + e.y * w1.y + e.z * w1.z + e.w * w1.w;
        }
#pragma unroll
        for (int o = 16; o; o >>= 1) {
            a0 += __shfl_xor_sync(0xffffffffu, a0, o);
            a1 += __shfl_xor_sync(0xffffffffu, a1, o);
        }
        if (lane == 0) { g_isqa[b * 2] = a0; g_isqa[b * 2 + 1] = a1; }
    }

    __syncthreads();

    // ---- parallel backpointer extraction (exact: same arithmetic as ref) ----
    {
        float trl[16];
#pragma unroll
        for (int i = 0; i < 16; i++) trl[i] = str[i];
#pragma unroll
        for (int p = 0; p < 2; p++) {
            int t = 1 + tid + p * 256;
            if (t < SF) {
                float4 d = sdelta[t - 1];
                unsigned byte = 0;
#pragma unroll
                for (int j = 0; j < 4; j++) {
                    float v0 = d.x + trl[j],     v1 = d.y + trl[4 + j];
                    float v2 = d.z + trl[8 + j], v3 = d.w + trl[12 + j];
                    float m01 = fmaxf(v0, v1); int i01 = (v1 > v0) ? 1 : 0;
                    float m23 = fmaxf(v2, v3); int i23 = (v3 > v2) ? 3 : 2;
                    int am = (m23 > m01) ? i23 : i01;   // ties -> lowest index
                    byte |= (unsigned)am << (2 * j);
                }
                sbp[t] = (unsigned char)byte;
            }
        }
    }
    __syncthreads();

    if (warp == 1) {
        // ---- parallel integer backtrace via tag-map composition ----
        float4 dl = sdelta[SF - 1];
        float s0 = dl.x + str[3], s1 = dl.y + str[7], s2 = dl.z + str[11], s3 = dl.w + str[15];
        int last = 0; float m = s0;
        if (s1 > m) { m = s1; last = 1; }
        if (s2 > m) { m = s2; last = 2; }
        if (s3 > m) { m = s3; last = 3; }

        const int c = lane;
        const int a0i = 16 * c + 1;
        unsigned char bb[16];
        unsigned F = 0xE4u;                 // identity map: 11 10 01 00
#pragma unroll
        for (int k = 15; k >= 0; k--) {
            int t = a0i + k;
            if (t < SF) {
                unsigned mp = sbp[t];
                bb[k] = (unsigned char)mp;
                unsigned nf = 0;
#pragma unroll
                for (int e = 0; e < 4; e++) {
                    unsigned fe = (F >> (2 * e)) & 3u;
                    nf |= ((mp >> (2 * fe)) & 3u) << (2 * e);
                }
                F = nf;
            }
        }
        // suffix scan: S_c = F_c o F_{c+1} o ... o F_31
        unsigned S = F;
#pragma unroll
        for (int s = 1; s < 32; s <<= 1) {
            unsigned o = __shfl_down_sync(0xffffffffu, S, s);
            if (c + s < 32) {
                unsigned ns = 0;
#pragma unroll
                for (int e = 0; e < 4; e++) {
                    unsigned be = (o >> (2 * e)) & 3u;
                    ns |= ((S >> (2 * be)) & 3u) << (2 * e);
                }
                S = ns;
            }
        }
        unsigned Snext = __shfl_down_sync(0xffffffffu, S, 1);
        int exitc = (c == 31) ? last : (int)((Snext >> (2 * last)) & 3u);

        unsigned pw = (c == 31) ? ((unsigned)last << 30) : 0u;
        int tag = exitc;
#pragma unroll
        for (int k = 15; k >= 0; k--) {
            int t = a0i + k;
            if (t < SF) {
                tag = (bb[k] >> (2 * tag)) & 3;
                pw |= (unsigned)tag << (2 * k);
            }
        }
        float* op = out + OFF_CPRED + b * SF + 16 * c;
#pragma unroll
        for (int q = 0; q < 4; q++) {
            float4 w4;
            w4.x = (float)((pw >> (8 * q)) & 3u);
            w4.y = (float)((pw >> (8 * q + 2)) & 3u);
            w4.z = (float)((pw >> (8 * q + 4)) & 3u);
            w4.w = (float)((pw >> (8 * q + 6)) & 3u);
            ((float4*)op)[q] = w4;
        }
    }
}

// ---------------------------------------------------------------------------
// Kernel C: isqa loss/pred, loss means, IsQA copy
// ---------------------------------------------------------------------------
__global__ __launch_bounds__(64) void finalize_kernel(
    const int* __restrict__ IsQA, const float* __restrict__ fc2_b,
    float* __restrict__ out)
{
    __shared__ float sA[BB], sC[BB];
    int b = threadIdx.x;
    float l0 = g_isqa[2 * b] + fc2_b[0];
    float l1 = g_isqa[2 * b + 1] + fc2_b[1];
    int q = IsQA[b];
    float m = fmaxf(l0, l1);
    float lse = m + logf(expf(l0 - m) + expf(l1 - m));
    float chosen = q ? l1 : l0;
    sA[b] = lse - chosen;
    sC[b] = g_Z[b] - g_gold[b];
    out[OFF_IPRED + b] = (l1 > l0) ? 1.f : 0.f;
    out[OFF_ISQA + b] = (float)q;
    __syncthreads();
    if (b == 0) {
        float s1 = 0.f, s2 = 0.f;
        for (int i = 0; i < BB; i++) { s1 += sA[i]; s2 += sC[i]; }
        out[OFF_ILOSS] = s1 * (1.f / BB);
        out[OFF_CLOSS] = s2 * (1.f / BB);
    }
}

extern "C" void kernel_launch(void* const* d_in, const int* in_sizes, int n_in,
                              void* d_out, int out_size)
{
    const float* emb    = (const float*)d_in[0];
    const int*   labels = (const int*)d_in[1];
    const int*   isqa   = (const int*)d_in[2];
    const float* fc2_W  = (const float*)d_in[3];
    const float* fc2_b  = (const float*)d_in[4];
    const float* crf_W  = (const float*)d_in[5];
    const float* crf_b  = (const float*)d_in[6];
    const float* trans  = (const float*)d_in[7];
    float* out = (float*)d_out;

    (void)in_sizes; (void)n_in; (void)out_size;

    feats_kernel<<<4096, 256>>>(emb, crf_W, crf_b);
    crf_kernel<<<BB, 256>>>(emb, labels, trans, fc2_W, out);
    finalize_kernel<<<1, 64>>>(isqa, fc2_b, out);
}

// round 7
// speedup vs baseline: 1.1544x; 1.1544x over previous
#include <cuda_runtime.h>
#include <math.h>

#define BB 64
#define S1 513
#define SF 512
#define HH 768
#define H4 192           // H/4 float4s per row

// output offsets (float32 flat tuple)
#define OFF_IPRED 0
#define OFF_CPRED 64
#define OFF_ILOSS 32832
#define OFF_CLOSS 32833
#define OFF_TAGS  32834
#define OFF_ISQA  65602

typedef unsigned long long u64;

__device__ __forceinline__ u64 pk2(float lo, float hi) {
    u64 r; asm("mov.b64 %0,{%1,%2};" : "=l"(r) : "f"(lo), "f"(hi)); return r;
}
__device__ __forceinline__ void upk2(u64 v, float& lo, float& hi) {
    asm("mov.b64 {%0,%1}, %2;" : "=f"(lo), "=f"(hi) : "l"(v));
}
__device__ __forceinline__ u64 fadd2(u64 a, u64 b) {
    u64 d; asm("add.rn.f32x2 %0,%1,%2;" : "=l"(d) : "l"(a), "l"(b)); return d;
}

// scratch (no allocations allowed)
__device__ float4 g_feats[BB * SF];
__device__ float  g_isqa[BB * 2];
__device__ float  g_Z[BB];
__device__ float  g_gold[BB];
__device__ float  g_lossA[BB];
__device__ float  g_lossC[BB];
__device__ unsigned g_ctr;

// ---------------------------------------------------------------------------
// Kernel A: feats = emb[:,1:] @ crf_W^T + crf_b
// 2 rows/warp, direct LDG with ALL 12 float4 loads hoisted (MLP=12/warp).
// FFMA + reduce order bit-identical to prior passing kernels.
// ---------------------------------------------------------------------------
__global__ __launch_bounds__(256) void feats_kernel(
    const float* __restrict__ emb, const float* __restrict__ crf_W,
    const float* __restrict__ crf_b)
{
    __shared__ float4 wc[4 * H4];
    for (int i = threadIdx.x; i < 4 * H4; i += 256) wc[i] = ((const float4*)crf_W)[i];
    if (blockIdx.x == 0 && threadIdx.x == 0) g_ctr = 0;   // reset loss counter
    __syncthreads();

    int warp = blockIdx.x * 8 + (threadIdx.x >> 5);
    int lane = threadIdx.x & 31;
    int row0 = warp * 2;                 // rows 0..32767, row = b*512 + s
    int b = row0 >> 9;
    int s0 = row0 & 511;
    const float4* eb = (const float4*)emb + ((size_t)b * S1 + 1 + s0) * H4;

    // hoist all 12 loads -> 12 outstanding LDG.128 per warp
    float4 E0 = eb[lane],           E1 = eb[lane + 32],      E2 = eb[lane + 64];
    float4 E3 = eb[lane + 96],      E4 = eb[lane + 128],     E5 = eb[lane + 160];
    float4 F0 = eb[H4 + lane],      F1 = eb[H4 + lane + 32], F2 = eb[H4 + lane + 64];
    float4 F3 = eb[H4 + lane + 96], F4 = eb[H4 + lane + 128], F5 = eb[H4 + lane + 160];

    float a[2][4];
#pragma unroll
    for (int r = 0; r < 2; r++)
#pragma unroll
        for (int j = 0; j < 4; j++) a[r][j] = 0.f;

#define FE(v, EV, FV) {                                                    \
        int k = lane + v * 32;                                             \
        _Pragma("unroll")                                                  \
        for (int j = 0; j < 4; j++) {                                      \
            float4 w = wc[j * H4 + k];                                     \
            a[0][j] += EV.x * w.x + EV.y * w.y + EV.z * w.z + EV.w * w.w;  \
            a[1][j] += FV.x * w.x + FV.y * w.y + FV.z * w.z + FV.w * w.w;  \
        } }
    FE(0, E0, F0) FE(1, E1, F1) FE(2, E2, F2)
    FE(3, E3, F3) FE(4, E4, F4) FE(5, E5, F5)
#undef FE

#pragma unroll
    for (int r = 0; r < 2; r++)
#pragma unroll
        for (int j = 0; j < 4; j++)
#pragma unroll
            for (int o = 16; o; o >>= 1)
                a[r][j] += __shfl_xor_sync(0xffffffffu, a[r][j], o);

    if (lane == 0) {
        float4 cb = __ldg((const float4*)crf_b);
#pragma unroll
        for (int r = 0; r < 2; r++) {
            float4 o;
            o.x = a[r][0] + cb.x; o.y = a[r][1] + cb.y;
            o.z = a[r][2] + cb.z; o.w = a[r][3] + cb.w;
            g_feats[row0 + r] = o;
        }
    }
}

// ---------------------------------------------------------------------------
// Kernel B: per batch-row CRF. 1 block/row, 8 warps:
//   warp0: segmented log-partition Z (8 segments x 4 basis columns)
//   warp1 lane0: Viterbi chain (bit-exact) storing deltas to smem
//   warp2: gold score + tags; warp3: isqa CLS GEMV
// then all 256: parallel bp extraction; warp1: parallel integer backtrace;
// warp2 lane0: per-b losses + last-block global loss reduction (deterministic).
// ---------------------------------------------------------------------------
__global__ __launch_bounds__(256) void crf_kernel(
    const float* __restrict__ emb, const int* __restrict__ labels,
    const float* __restrict__ transitions, const float* __restrict__ fc2_W,
    const float* __restrict__ fc2_b, const int* __restrict__ IsQA,
    float* __restrict__ out)
{
    const int b = blockIdx.x;
    __shared__ float4 sfeat[SF];        // 8 KB, plain t index
    __shared__ float4 sE[SF];           // 8 KB, exp(feat_t), seg-interleaved
    __shared__ float4 sdelta[SF];       // 8 KB
    __shared__ unsigned char sbp[SF];
    __shared__ float str[16];
    __shared__ float sEt[16];
    __shared__ float4 scomp[32];        // segment matrices (columns)
    __shared__ float  scC[8];           // segment exponents

    const int tid = threadIdx.x;
    const float4* gf = &g_feats[b * SF];

    if (tid < 16) {
        float tv = transitions[tid];
        str[tid] = tv;
        sEt[tid] = expf(tv);
    }
    // prologue: stage feats + exp(feats) (interleaved slot = k*8+s)
#pragma unroll
    for (int p = 0; p < 2; p++) {
        int t = tid + p * 256;
        float4 f = gf[t];
        sfeat[t] = f;
        if (t >= 1) {
            int s = (t - 1) >> 6, k = (t - 1) & 63;
            sE[k * 8 + s] = make_float4(__expf(f.x), __expf(f.y), __expf(f.z), __expf(f.w));
        }
    }
    __syncthreads();

    const int warp = tid >> 5, lane = tid & 31;

    if (warp == 0) {
        // ---- segmented Z: lane = (segment s, basis column c) ----
        const int s = lane >> 2, c = lane & 3;
        float Et[16];
#pragma unroll
        for (int i = 0; i < 16; i++) Et[i] = sEt[i];
        float v0 = (c == 0) ? 1.f : 0.f;
        float v1 = (c == 1) ? 1.f : 0.f;
        float v2 = (c == 2) ? 1.f : 0.f;
        float v3 = (c == 3) ? 1.f : 0.f;
        float C2 = 0.f;
        const int nsteps = (s < 7) ? 64 : 63;
        for (int k = 0; k < 64; k++) {
            if (k < nsteps) {
                float4 E = sE[k * 8 + s];
                float q0 = v0 * Et[0] + v1 * Et[4] + v2 * Et[8]  + v3 * Et[12];
                float q1 = v0 * Et[1] + v1 * Et[5] + v2 * Et[9]  + v3 * Et[13];
                float q2 = v0 * Et[2] + v1 * Et[6] + v2 * Et[10] + v3 * Et[14];
                float q3 = v0 * Et[3] + v1 * Et[7] + v2 * Et[11] + v3 * Et[15];
                v0 = q0 * E.x; v1 = q1 * E.y; v2 = q2 * E.z; v3 = q3 * E.w;
            }
            if ((k & 15) == 15) {
                float m = fmaxf(fmaxf(v0, v1), fmaxf(v2, v3));
                m = fmaxf(m, __shfl_xor_sync(0xffffffffu, m, 1));
                m = fmaxf(m, __shfl_xor_sync(0xffffffffu, m, 2));
                int e = (__float_as_int(m) >> 23) - 127;
                C2 += (float)e;
                float sc = __int_as_float((127 - e) << 23);
                v0 *= sc; v1 *= sc; v2 *= sc; v3 *= sc;
            }
        }
        scomp[lane] = make_float4(v0, v1, v2, v3);  // column c of A_s
        if (c == 0) scC[s] = C2;
        __syncwarp(0xffffffffu);
        if (lane == 0) {
            float4 f0 = sfeat[0];
            float p0 = __expf(f0.x + str[8]);
            float p1 = __expf(f0.y + str[9]);
            float p2 = __expf(f0.z + str[10]);
            float p3 = __expf(f0.w + str[11]);
            float Ct = 0.f;
#pragma unroll
            for (int ss = 0; ss < 8; ss++) {
                float4 c0 = scomp[4 * ss], c1 = scomp[4 * ss + 1];
                float4 c2 = scomp[4 * ss + 2], c3 = scomp[4 * ss + 3];
                float q0 = p0 * c0.x + p1 * c1.x + p2 * c2.x + p3 * c3.x;
                float q1 = p0 * c0.y + p1 * c1.y + p2 * c2.y + p3 * c3.y;
                float q2 = p0 * c0.z + p1 * c1.z + p2 * c2.z + p3 * c3.z;
                float q3 = p0 * c0.w + p1 * c1.w + p2 * c2.w + p3 * c3.w;
                Ct += scC[ss];
                float m = fmaxf(fmaxf(q0, q1), fmaxf(q2, q3));
                int e = (__float_as_int(m) >> 23) - 127;
                Ct += (float)e;
                float sc = __int_as_float((127 - e) << 23);
                p0 = q0 * sc; p1 = q1 * sc; p2 = q2 * sc; p3 = q3 * sc;
            }
            float sum = p0 * sEt[3] + p1 * sEt[7] + p2 * sEt[11] + p3 * sEt[15];
            g_Z[b] = (Ct + __log2f(sum)) * 0.69314718055994530942f;
        }
    }

    if (warp == 1 && lane == 0) {
        // ---- Viterbi chain: bit-exact (ADD2 componentwise == scalar FADD) ----
        float tr[16];
#pragma unroll
        for (int i = 0; i < 16; i++) tr[i] = str[i];
        u64 TA0 = pk2(tr[0], tr[4]),   TA1 = pk2(tr[1], tr[5]);
        u64 TA2 = pk2(tr[2], tr[6]),   TA3 = pk2(tr[3], tr[7]);
        u64 TB0 = pk2(tr[8], tr[12]),  TB1 = pk2(tr[9], tr[13]);
        u64 TB2 = pk2(tr[10], tr[14]), TB3 = pk2(tr[11], tr[15]);

        float4 f0 = sfeat[0];
        float d0 = f0.x + tr[8], d1 = f0.y + tr[9], d2 = f0.z + tr[10], d3 = f0.w + tr[11];
        sdelta[0] = make_float4(d0, d1, d2, d3);
        u64 D01 = pk2(d0, d1), D23 = pk2(d2, d3);

#pragma unroll 8
        for (int t = 1; t < SF; t++) {
            float4 f = sfeat[t];
            u64 a0 = fadd2(D01, TA0), a1 = fadd2(D01, TA1);
            u64 a2 = fadd2(D01, TA2), a3 = fadd2(D01, TA3);
            u64 b0 = fadd2(D23, TB0), b1 = fadd2(D23, TB1);
            u64 b2 = fadd2(D23, TB2), b3 = fadd2(D23, TB3);
            float x0,x1,y0,y1,x2,x3,y2,y3,x4,x5,y4,y5,x6,x7,y6,y7;
            upk2(a0,x0,x1); upk2(b0,y0,y1);
            upk2(a1,x2,x3); upk2(b1,y2,y3);
            upk2(a2,x4,x5); upk2(b2,y4,y5);
            upk2(a3,x6,x7); upk2(b3,y6,y7);
            float n0 = fmaxf(fmaxf(x0,x1), fmaxf(y0,y1)) + f.x;
            float n1 = fmaxf(fmaxf(x2,x3), fmaxf(y2,y3)) + f.y;
            float n2 = fmaxf(fmaxf(x4,x5), fmaxf(y4,y5)) + f.z;
            float n3 = fmaxf(fmaxf(x6,x7), fmaxf(y6,y7)) + f.w;
            D01 = pk2(n0, n1); D23 = pk2(n2, n3);
            sdelta[t] = make_float4(n0, n1, n2, n3);
        }
    }

    if (warp == 2) {
        // ---- gold score + tags output ----
        float acc = 0.f;
        const int* lb = labels + b * S1;
        const float* sff = (const float*)sfeat;
        for (int t = lane; t < SF; t += 32) {
            int tg = lb[1 + t];
            acc += sff[t * 4 + tg];
            out[OFF_TAGS + b * SF + t] = (float)tg;
            if (t > 0) { int tp = lb[t]; acc += str[tp * 4 + tg]; }
            else       { acc += str[8 + tg]; }                 // START -> tag0
            if (t == SF - 1) acc += str[tg * 4 + 3];           // tag_last -> STOP
        }
#pragma unroll
        for (int o = 16; o; o >>= 1) acc += __shfl_xor_sync(0xffffffffu, acc, o);
        if (lane == 0) g_gold[b] = acc;
    }

    if (warp == 3) {
        // ---- isqa logits for this row's CLS token (overlapped) ----
        const float4* e4 = (const float4*)emb + (size_t)b * S1 * H4;
        const float4* w4 = (const float4*)fc2_W;
        float a0 = 0.f, a1 = 0.f;
#pragma unroll
        for (int v = 0; v < 6; v++) {
            int k = lane + v * 32;
            float4 e = e4[k];
            float4 w0 = __ldg(w4 + k);
            float4 w1 = __ldg(w4 + H4 + k);
            a0 += e.x * w0.x + e.y * w0.y + e.z * w0.z + e.w * w0.w;
            a1 += e.x * w1.x + e.y * w1.y + e.z * w1.z + e.w * w1.w;
        }
#pragma unroll
        for (int o = 16; o; o >>= 1) {
            a0 += __shfl_xor_sync(0xffffffffu, a0, o);
            a1 += __shfl_xor_sync(0xffffffffu, a1, o);
        }
        if (lane == 0) { g_isqa[b * 2] = a0; g_isqa[b * 2 + 1] = a1; }
    }

    __syncthreads();

    // ---- parallel backpointer extraction (exact: same arithmetic as ref) ----
    {
        float trl[16];
#pragma unroll
        for (int i = 0; i < 16; i++) trl[i] = str[i];
#pragma unroll
        for (int p = 0; p < 2; p++) {
            int t = 1 + tid + p * 256;
            if (t < SF) {
                float4 d = sdelta[t - 1];
                unsigned byte = 0;
#pragma unroll
                for (int j = 0; j < 4; j++) {
                    float v0 = d.x + trl[j],     v1 = d.y + trl[4 + j];
                    float v2 = d.z + trl[8 + j], v3 = d.w + trl[12 + j];
                    float m01 = fmaxf(v0, v1); int i01 = (v1 > v0) ? 1 : 0;
                    float m23 = fmaxf(v2, v3); int i23 = (v3 > v2) ? 3 : 2;
                    int am = (m23 > m01) ? i23 : i01;   // ties -> lowest index
                    byte |= (unsigned)am << (2 * j);
                }
                sbp[t] = (unsigned char)byte;
            }
        }
    }
    __syncthreads();

    if (warp == 1) {
        // ---- parallel integer backtrace via tag-map composition ----
        float4 dl = sdelta[SF - 1];
        float s0 = dl.x + str[3], s1 = dl.y + str[7], s2 = dl.z + str[11], s3 = dl.w + str[15];
        int last = 0; float m = s0;
        if (s1 > m) { m = s1; last = 1; }
        if (s2 > m) { m = s2; last = 2; }
        if (s3 > m) { m = s3; last = 3; }

        const int c = lane;
        const int a0i = 16 * c + 1;
        unsigned char bb[16];
        unsigned F = 0xE4u;                 // identity map: 11 10 01 00
#pragma unroll
        for (int k = 15; k >= 0; k--) {
            int t = a0i + k;
            if (t < SF) {
                unsigned mp = sbp[t];
                bb[k] = (unsigned char)mp;
                unsigned nf = 0;
#pragma unroll
                for (int e = 0; e < 4; e++) {
                    unsigned fe = (F >> (2 * e)) & 3u;
                    nf |= ((mp >> (2 * fe)) & 3u) << (2 * e);
                }
                F = nf;
            }
        }
        // suffix scan: S_c = F_c o F_{c+1} o ... o F_31
        unsigned S = F;
#pragma unroll
        for (int s = 1; s < 32; s <<= 1) {
            unsigned o = __shfl_down_sync(0xffffffffu, S, s);
            if (c + s < 32) {
                unsigned ns = 0;
#pragma unroll
                for (int e = 0; e < 4; e++) {
                    unsigned be = (o >> (2 * e)) & 3u;
                    ns |= ((S >> (2 * be)) & 3u) << (2 * e);
                }
                S = ns;
            }
        }
        unsigned Snext = __shfl_down_sync(0xffffffffu, S, 1);
        int exitc = (c == 31) ? last : (int)((Snext >> (2 * last)) & 3u);

        unsigned pw = (c == 31) ? ((unsigned)last << 30) : 0u;
        int tag = exitc;
#pragma unroll
        for (int k = 15; k >= 0; k--) {
            int t = a0i + k;
            if (t < SF) {
                tag = (bb[k] >> (2 * tag)) & 3;
                pw |= (unsigned)tag << (2 * k);
            }
        }
        float* op = out + OFF_CPRED + b * SF + 16 * c;
#pragma unroll
        for (int q = 0; q < 4; q++) {
            float4 w4;
            w4.x = (float)((pw >> (8 * q)) & 3u);
            w4.y = (float)((pw >> (8 * q + 2)) & 3u);
            w4.z = (float)((pw >> (8 * q + 4)) & 3u);
            w4.w = (float)((pw >> (8 * q + 6)) & 3u);
            ((float4*)op)[q] = w4;
        }
    }

    if (warp == 2 && lane == 0) {
        // ---- per-b losses + deterministic last-block reduction ----
        float l0 = g_isqa[2 * b] + fc2_b[0];
        float l1 = g_isqa[2 * b + 1] + fc2_b[1];
        int q = IsQA[b];
        float mm = fmaxf(l0, l1);
        float lse = mm + logf(expf(l0 - mm) + expf(l1 - mm));
        float chosen = q ? l1 : l0;
        g_lossA[b] = lse - chosen;
        g_lossC[b] = g_Z[b] - g_gold[b];
        out[OFF_IPRED + b] = (l1 > l0) ? 1.f : 0.f;
        out[OFF_ISQA + b] = (float)q;
        __threadfence();
        unsigned old = atomicAdd(&g_ctr, 1u);
        if (old == BB - 1) {
            __threadfence();
            float s1 = 0.f, s2 = 0.f;
            for (int i = 0; i < BB; i++) { s1 += g_lossA[i]; s2 += g_lossC[i]; }
            out[OFF_ILOSS] = s1 * (1.f / BB);
            out[OFF_CLOSS] = s2 * (1.f / BB);
        }
    }
}

extern "C" void kernel_launch(void* const* d_in, const int* in_sizes, int n_in,
                              void* d_out, int out_size)
{
    const float* emb    = (const float*)d_in[0];
    const int*   labels = (const int*)d_in[1];
    const int*   isqa   = (const int*)d_in[2];
    const float* fc2_W  = (const float*)d_in[3];
    const float* fc2_b  = (const float*)d_in[4];
    const float* crf_W  = (const float*)d_in[5];
    const float* crf_b  = (const float*)d_in[6];
    const float* trans  = (const float*)d_in[7];
    float* out = (float*)d_out;

    (void)in_sizes; (void)n_in; (void)out_size;

    feats_kernel<<<2048, 256>>>(emb, crf_W, crf_b);
    crf_kernel<<<BB, 256>>>(emb, labels, trans, fc2_W, fc2_b, isqa, out);
}